// round 12
// baseline (speedup 1.0000x reference)
#include <cuda_runtime.h>
#include <cuda_fp16.h>
#include <cstdint>
#include <math.h>

// ---------------------------------------------------------------------------
// LinearSelfAttention — round 12:
//   * feat3 reverted to R10 staged-store version (coalesced epilogue)
//   * tc_gemm1: 3-stage cp.async ring (2 CTAs/SM preserved)
//   * keeps R11 z_hmma 2 CTAs/SM + fused split/wtrans
//   (no numeric change: rel_err must stay 0.000748069)
// ---------------------------------------------------------------------------

#define B_ 4
#define L_ 4096
#define H_ 16
#define D_ 64
#define M_ 128
#define DM_ 1024
#define NCHUNK 8
#define LC_ (L_ / NCHUNK)    // 512

#define NORMALIZER 0.35355339059327373f
#define RATIO      0.08838834764831845f

// ----- fp32 scratch -----
__device__ float g_part[(size_t)B_ * H_ * NCHUNK * 2 * M_ * D_];
__device__ float g_nf  [(size_t)B_ * L_ * H_];

// ----- fp16 scratch -----
#define NROW16 ((size_t)B_ * L_ * DM_)
__device__ __half g_qp16 [(size_t)B_ * L_ * H_ * 2 * M_];
__device__ __half g_kh16 [(size_t)B_ * L_ * H_ * 2 * M_];
__device__ __half g_kl16 [(size_t)B_ * L_ * H_ * 2 * M_];
__device__ __half g_vh16 [NROW16];
__device__ __half g_vl16 [NROW16];
__device__ __half g_kvT16[(size_t)B_ * H_ * D_ * 2 * M_];
__device__ __half g_pph  [NROW16];
__device__ __half g_ppl  [NROW16];
__device__ __half g_sph  [NROW16];
__device__ __half g_spl  [NROW16];
__device__ __half g_prjh [(size_t)M_ * D_];
__device__ __half g_prjl [(size_t)M_ * D_];
__device__ __half g_x16h [NROW16];
__device__ __half g_p16h [NROW16];
__device__ __half g_p16l [NROW16];
__device__ __half g_s16h [NROW16];
__device__ __half g_s16l [NROW16];
__device__ __half g_z16h [NROW16];
__device__ __half g_WvTh [(size_t)DM_ * DM_];
__device__ __half g_WpTh [(size_t)DM_ * DM_];
__device__ __half g_WpTl [(size_t)DM_ * DM_];
__device__ __half g_WoTh [(size_t)DM_ * DM_];

// ===========================================================================
// PTX helpers
// ===========================================================================
__device__ __forceinline__ uint32_t smem_u32(const void* p) {
    uint32_t a;
    asm("{ .reg .u64 t; cvta.to.shared.u64 t, %1; cvt.u32.u64 %0, t; }"
        : "=r"(a) : "l"(p));
    return a;
}
__device__ __forceinline__ void ldmatrix_x4(uint32_t* r, uint32_t addr) {
    asm volatile("ldmatrix.sync.aligned.m8n8.x4.shared.b16 {%0,%1,%2,%3}, [%4];"
                 : "=r"(r[0]), "=r"(r[1]), "=r"(r[2]), "=r"(r[3]) : "r"(addr));
}
__device__ __forceinline__ void ldmatrix_x2(uint32_t* r, uint32_t addr) {
    asm volatile("ldmatrix.sync.aligned.m8n8.x2.shared.b16 {%0,%1}, [%2];"
                 : "=r"(r[0]), "=r"(r[1]) : "r"(addr));
}
__device__ __forceinline__ void ldmatrix_x4_t(uint32_t* r, uint32_t addr) {
    asm volatile("ldmatrix.sync.aligned.m8n8.x4.trans.shared.b16 {%0,%1,%2,%3}, [%4];"
                 : "=r"(r[0]), "=r"(r[1]), "=r"(r[2]), "=r"(r[3]) : "r"(addr));
}
__device__ __forceinline__ void ldmatrix_x2_t(uint32_t* r, uint32_t addr) {
    asm volatile("ldmatrix.sync.aligned.m8n8.x2.trans.shared.b16 {%0,%1}, [%2];"
                 : "=r"(r[0]), "=r"(r[1]) : "r"(addr));
}
__device__ __forceinline__ void mma16816(float* c, const uint32_t* a,
                                         const uint32_t* b) {
    asm volatile(
        "mma.sync.aligned.m16n8k16.row.col.f32.f16.f16.f32 "
        "{%0,%1,%2,%3}, {%4,%5,%6,%7}, {%8,%9}, {%0,%1,%2,%3};"
        : "+f"(c[0]), "+f"(c[1]), "+f"(c[2]), "+f"(c[3])
        : "r"(a[0]), "r"(a[1]), "r"(a[2]), "r"(a[3]), "r"(b[0]), "r"(b[1]));
}

#define KC_ 64
#define ROWB 144
#define TB_ (128 * ROWB)               // 18432 per 128x64 tile

// ===========================================================================
// tc_gemm1: C = A @ B^T, single term, 3-stage ring, 2 CTAs/SM.
// ===========================================================================
#define G1_STAGE (2 * TB_)             // 36864
#define G1_SMEM (3 * G1_STAGE)         // 110592

__global__ __launch_bounds__(256, 2)
void tc_gemm1(const __half* __restrict__ A0, const __half* __restrict__ B0,
              float* __restrict__ C, __half* __restrict__ Ch,
              __half* __restrict__ Cl, int Nld, int K, int out16)
{
    extern __shared__ char smem[];
    const uint32_t sb = smem_u32(smem);
    const int tid = threadIdx.x;
    const int wid = tid >> 5;
    const int lane = tid & 31;
    const int wm = wid & 1;
    const int wn = wid >> 1;
    const int n0 = blockIdx.x * 128;
    const int m0 = blockIdx.y * 128;

    const uint32_t a_off = (uint32_t)((((lane >> 3) & 1) * 8 + (lane & 7)) * ROWB
                                      + ((lane >> 4) * 8) * 2);
    const int bl_ = lane & 15;
    const uint32_t b_off = (uint32_t)(((bl_ & 7)) * ROWB + (((bl_ >> 3) & 1) * 8) * 2);

    float acc[4][4][4];
#pragma unroll
    for (int i = 0; i < 4; i++)
#pragma unroll
        for (int j = 0; j < 4; j++)
#pragma unroll
            for (int q = 0; q < 4; q++) acc[i][j][q] = 0.0f;

    const int nch = K / KC_;   // 16

    auto load_stage = [&](int s, int chunk) {
        const int k0 = chunk * KC_;
        const uint32_t stage = sb + s * G1_STAGE;
#pragma unroll
        for (int buf = 0; buf < 2; buf++) {
            const __half* src = buf ? B0 : A0;
            const int r0 = buf ? n0 : m0;
            const uint32_t tb = stage + buf * TB_;
#pragma unroll
            for (int j = 0; j < 4; j++) {
                const int c = tid + j * 256;
                const int row = c >> 3;
                const int seg = c & 7;
                const uint32_t dst = tb + (uint32_t)(row * ROWB + seg * 16);
                const __half* sp = src + (size_t)(r0 + row) * K + k0 + seg * 8;
                asm volatile("cp.async.cg.shared.global [%0], [%1], 16;\n"
                             :: "r"(dst), "l"(sp));
            }
        }
        asm volatile("cp.async.commit_group;\n");
    };

    // prime 2 stages
    load_stage(0, 0);
    load_stage(1, 1);

    for (int i = 0; i < nch; i++) {
        const int s = i % 3;
        if (i + 2 < nch) {
            load_stage((i + 2) % 3, i + 2);
            asm volatile("cp.async.wait_group 2;\n");
        } else if (i + 1 < nch) {
            asm volatile("cp.async.wait_group 1;\n");
        } else {
            asm volatile("cp.async.wait_group 0;\n");
        }
        __syncthreads();

        const uint32_t stage = sb + s * G1_STAGE;
        const uint32_t Ah = stage;
        const uint32_t Bh = stage + TB_;
        const uint32_t a_row = (uint32_t)(wm * 64 * ROWB);
        const uint32_t b_row = (uint32_t)(wn * 32 * ROWB);

#pragma unroll
        for (int kk = 0; kk < 4; kk++) {
            const uint32_t kb = (uint32_t)(kk * 32);
            uint32_t ah[4][4], bh[4][2];
#pragma unroll
            for (int mf = 0; mf < 4; mf++)
                ldmatrix_x4(ah[mf], Ah + a_row + (uint32_t)(mf * 16 * ROWB) + kb + a_off);
#pragma unroll
            for (int nf = 0; nf < 4; nf++)
                ldmatrix_x2(bh[nf], Bh + b_row + (uint32_t)(nf * 8 * ROWB) + kb + b_off);
#pragma unroll
            for (int mf = 0; mf < 4; mf++)
#pragma unroll
                for (int nf = 0; nf < 4; nf++)
                    mma16816(acc[mf][nf], ah[mf], bh[nf]);
        }
        __syncthreads();
    }

    const int mrow = lane >> 2;
    const int ncol = (lane & 3) * 2;
#pragma unroll
    for (int mf = 0; mf < 4; mf++) {
        const int gm = m0 + wm * 64 + mf * 16 + mrow;
#pragma unroll
        for (int nf = 0; nf < 4; nf++) {
            const int gn = n0 + wn * 32 + nf * 8 + ncol;
            if (!out16) {
                *(float2*)(C + (size_t)gm * Nld + gn) =
                    make_float2(acc[mf][nf][0], acc[mf][nf][1]);
                *(float2*)(C + (size_t)(gm + 8) * Nld + gn) =
                    make_float2(acc[mf][nf][2], acc[mf][nf][3]);
            } else {
#pragma unroll
                for (int hh = 0; hh < 2; hh++) {
                    const float v0 = acc[mf][nf][hh * 2 + 0];
                    const float v1 = acc[mf][nf][hh * 2 + 1];
                    const __half h0 = __float2half_rn(v0);
                    const __half h1 = __float2half_rn(v1);
                    const __half e0 = __float2half_rn(v0 - __half2float(h0));
                    const __half e1 = __float2half_rn(v1 - __half2float(h1));
                    const size_t o = (size_t)(gm + hh * 8) * Nld + gn;
                    *(__half2*)(Ch + o) = __halves2half2(h0, h1);
                    *(__half2*)(Cl + o) = __halves2half2(e0, e1);
                }
            }
        }
    }
}

// ===========================================================================
// tc_gemm_pair (unchanged)
// ===========================================================================
#define GP_STAGE (6 * TB_)
#define GP_SMEM (2 * GP_STAGE)

__global__ __launch_bounds__(256, 1)
void tc_gemm_pair(const __half* __restrict__ Ap0, const __half* __restrict__ Ap1,
                  const __half* __restrict__ As0, const __half* __restrict__ As1,
                  const __half* __restrict__ B0, const __half* __restrict__ B1,
                  __half* __restrict__ Chp, __half* __restrict__ Clp,
                  __half* __restrict__ Chs, __half* __restrict__ Cls,
                  int Nld, int K)
{
    extern __shared__ char smem[];
    const uint32_t sb = smem_u32(smem);
    const int tid = threadIdx.x;
    const int wid = tid >> 5;
    const int lane = tid & 31;
    const int wm = wid & 1;
    const int wn = wid >> 1;
    const int n0 = blockIdx.x * 128;
    const int m0 = blockIdx.y * 128;

    const __half* srcs[6] = {Ap0, Ap1, As0, As1, B0, B1};

    const uint32_t a_off = (uint32_t)((((lane >> 3) & 1) * 8 + (lane & 7)) * ROWB
                                      + ((lane >> 4) * 8) * 2);
    const int bl_ = lane & 15;
    const uint32_t b_off = (uint32_t)(((bl_ & 7)) * ROWB + (((bl_ >> 3) & 1) * 8) * 2);

    float accp[4][4][4], accs[4][4][4];
#pragma unroll
    for (int i = 0; i < 4; i++)
#pragma unroll
        for (int j = 0; j < 4; j++)
#pragma unroll
            for (int q = 0; q < 4; q++) { accp[i][j][q] = 0.0f; accs[i][j][q] = 0.0f; }

    const int nch = K / KC_;

    auto load_stage = [&](int s, int chunk) {
        const int k0 = chunk * KC_;
        const uint32_t stage = sb + s * GP_STAGE;
#pragma unroll
        for (int buf = 0; buf < 6; buf++) {
            const __half* src = srcs[buf];
            const int r0 = (buf < 4) ? m0 : n0;
            const uint32_t tb = stage + buf * TB_;
#pragma unroll
            for (int j = 0; j < 4; j++) {
                const int c = tid + j * 256;
                const int row = c >> 3;
                const int seg = c & 7;
                const uint32_t dst = tb + (uint32_t)(row * ROWB + seg * 16);
                const __half* sp = src + (size_t)(r0 + row) * K + k0 + seg * 8;
                asm volatile("cp.async.cg.shared.global [%0], [%1], 16;\n"
                             :: "r"(dst), "l"(sp));
            }
        }
        asm volatile("cp.async.commit_group;\n");
    };

    load_stage(0, 0);

    for (int i = 0; i < nch; i++) {
        const int s = i & 1;
        if (i + 1 < nch) {
            load_stage(s ^ 1, i + 1);
            asm volatile("cp.async.wait_group 1;\n");
        } else {
            asm volatile("cp.async.wait_group 0;\n");
        }
        __syncthreads();

        const uint32_t stage = sb + s * GP_STAGE;
        const uint32_t Bh = stage + 4 * TB_;
        const uint32_t Bl = stage + 5 * TB_;
        const uint32_t a_row = (uint32_t)(wm * 64 * ROWB);
        const uint32_t b_row = (uint32_t)(wn * 32 * ROWB);

#pragma unroll
        for (int kk = 0; kk < 4; kk++) {
            const uint32_t kb = (uint32_t)(kk * 32);
            uint32_t bh[4][2], blr[4][2];
#pragma unroll
            for (int nf = 0; nf < 4; nf++) {
                const uint32_t ro = b_row + (uint32_t)(nf * 8 * ROWB) + kb + b_off;
                ldmatrix_x2(bh[nf], Bh + ro);
                ldmatrix_x2(blr[nf], Bl + ro);
            }
#pragma unroll
            for (int set = 0; set < 2; set++) {
                const uint32_t AH = stage + (set ? 2 : 0) * TB_;
                const uint32_t AL = stage + (set ? 3 : 1) * TB_;
                uint32_t ah[4][4], al[4][4];
#pragma unroll
                for (int mf = 0; mf < 4; mf++) {
                    const uint32_t ro = a_row + (uint32_t)(mf * 16 * ROWB) + kb + a_off;
                    ldmatrix_x4(ah[mf], AH + ro);
                    ldmatrix_x4(al[mf], AL + ro);
                }
#pragma unroll
                for (int mf = 0; mf < 4; mf++)
#pragma unroll
                    for (int nf = 0; nf < 4; nf++) {
                        if (set == 0) {
                            mma16816(accp[mf][nf], ah[mf], bh[nf]);
                            mma16816(accp[mf][nf], al[mf], bh[nf]);
                            mma16816(accp[mf][nf], ah[mf], blr[nf]);
                        } else {
                            mma16816(accs[mf][nf], ah[mf], bh[nf]);
                            mma16816(accs[mf][nf], al[mf], bh[nf]);
                            mma16816(accs[mf][nf], ah[mf], blr[nf]);
                        }
                    }
            }
        }
        __syncthreads();
    }

    const int mrow = lane >> 2;
    const int ncol = (lane & 3) * 2;
#pragma unroll
    for (int set = 0; set < 2; set++) {
        __half* Ch = set ? Chs : Chp;
        __half* Cl = set ? Cls : Clp;
#pragma unroll
        for (int mf = 0; mf < 4; mf++) {
            const int gm = m0 + wm * 64 + mf * 16 + mrow;
#pragma unroll
            for (int nf = 0; nf < 4; nf++) {
                const int gn = n0 + wn * 32 + nf * 8 + ncol;
#pragma unroll
                for (int hh = 0; hh < 2; hh++) {
                    const float v0 = set ? accs[mf][nf][hh * 2 + 0]
                                         : accp[mf][nf][hh * 2 + 0];
                    const float v1 = set ? accs[mf][nf][hh * 2 + 1]
                                         : accp[mf][nf][hh * 2 + 1];
                    const __half h0 = __float2half_rn(v0);
                    const __half h1 = __float2half_rn(v1);
                    const __half e0 = __float2half_rn(v0 - __half2float(h0));
                    const __half e1 = __float2half_rn(v1 - __half2float(h1));
                    const size_t o = (size_t)(gm + hh * 8) * Nld + gn;
                    *(__half2*)(Ch + o) = __halves2half2(h0, h1);
                    *(__half2*)(Cl + o) = __halves2half2(e0, e1);
                }
            }
        }
    }
}

// ===========================================================================
// fused split / transpose helpers (unchanged from R11)
// ===========================================================================
__global__ __launch_bounds__(256)
void split_all_kernel(const float* __restrict__ x, const float* __restrict__ pft,
                      const float* __restrict__ psl,
                      __half* __restrict__ xh, __half* __restrict__ ph,
                      __half* __restrict__ pl, __half* __restrict__ sh,
                      __half* __restrict__ sl)
{
    const int z = blockIdx.y;
    const float* src = (z == 0) ? x : (z == 1 ? pft : psl);
    __half* hi = (z == 0) ? xh : (z == 1 ? ph : sh);
    __half* lo = (z == 1) ? pl : sl;

    const size_t i0 = ((size_t)blockIdx.x * 256 + threadIdx.x) * 4;
    float4 v = *(const float4*)(src + i0);
    float f[4] = {v.x, v.y, v.z, v.w};
    __half ha0 = __float2half_rn(f[0]);
    __half ha1 = __float2half_rn(f[1]);
    __half ha2 = __float2half_rn(f[2]);
    __half ha3 = __float2half_rn(f[3]);
    *(__half2*)(hi + i0)     = __halves2half2(ha0, ha1);
    *(__half2*)(hi + i0 + 2) = __halves2half2(ha2, ha3);
    if (z != 0) {
        *(__half2*)(lo + i0) = __halves2half2(
            __float2half_rn(f[0] - __half2float(ha0)),
            __float2half_rn(f[1] - __half2float(ha1)));
        *(__half2*)(lo + i0 + 2) = __halves2half2(
            __float2half_rn(f[2] - __half2float(ha2)),
            __float2half_rn(f[3] - __half2float(ha3)));
    }
}

__global__ __launch_bounds__(256)
void wtrans_all_kernel(const float* __restrict__ Wv, const float* __restrict__ Wp,
                       const float* __restrict__ Wo,
                       __half* __restrict__ wvh, __half* __restrict__ wph,
                       __half* __restrict__ wpl, __half* __restrict__ woh)
{
    const int z = blockIdx.z;
    const float* W = (z == 0) ? Wv : (z == 1 ? Wp : Wo);
    __half* th = (z == 0) ? wvh : (z == 1 ? wph : woh);
    __half* tl = (z == 1) ? wpl : (__half*)0;

    __shared__ float tile[32][33];
    const int tx = threadIdx.x & 31;
    const int ty = threadIdx.x >> 5;
    const int n0 = blockIdx.x * 32;
    const int k0 = blockIdx.y * 32;
#pragma unroll
    for (int i = 0; i < 4; i++)
        tile[ty + i * 8][tx] = W[(size_t)(k0 + ty + i * 8) * DM_ + n0 + tx];
    __syncthreads();
#pragma unroll
    for (int i = 0; i < 4; i++) {
        const int n = ty + i * 8;
        float v = tile[tx][n];
        __half h = __float2half_rn(v);
        const size_t o = (size_t)(n0 + n) * DM_ + k0 + tx;
        th[o] = h;
        if (tl) tl[o] = __float2half_rn(v - __half2float(h));
    }
}

__global__ __launch_bounds__(256)
void proj_split_kernel(const float* __restrict__ proj, __half* __restrict__ ph,
                       __half* __restrict__ pl)
{
    const int i = blockIdx.x * 256 + threadIdx.x;
    if (i < M_ * D_) {
        const float v = NORMALIZER * proj[i];
        const __half h = __float2half_rn(v);
        ph[i] = h;
        pl[i] = __float2half_rn(v - __half2float(h));
    }
}

// ===========================================================================
// feat3 — R10 staged-store version (coalesced epilogue), 1 CTA/SM
// ===========================================================================
#define F3_AT (128 * ROWB)
#define F3_STAGE_OFF (6 * F3_AT)
#define F3_SMEM (F3_STAGE_OFF + 8 * 16 * 256 * 2)   // 176128

__global__ __launch_bounds__(256, 1)
void feat3_kernel(const __half* __restrict__ pph, const __half* __restrict__ ppl,
                  const __half* __restrict__ sph, const __half* __restrict__ spl,
                  const __half* __restrict__ prjh, const __half* __restrict__ prjl,
                  const float* __restrict__ scale, const float* __restrict__ offs,
                  __half* __restrict__ qp16, __half* __restrict__ kh16,
                  __half* __restrict__ kl16, float* __restrict__ nf)
{
    extern __shared__ char smem[];
    __shared__ float nfp[256];
    const uint32_t sb = smem_u32(smem);
    const int tid = threadIdx.x;
    const int wid = tid >> 5;
    const int lane = tid & 31;
    const int h = blockIdx.y;
    const int r0 = blockIdx.x * 128;
    const float s = scale[h];
    const float off = offs[h];

    {
        const __half* abuf[4] = {pph, ppl, sph, spl};
#pragma unroll
        for (int buf = 0; buf < 4; buf++) {
#pragma unroll
            for (int j = 0; j < 4; j++) {
                const int c = tid + j * 256;
                const int row = c >> 3;
                const int seg = c & 7;
                const uint32_t dst = sb + (uint32_t)(buf * F3_AT + row * ROWB + seg * 16);
                const __half* sp_ = abuf[buf] + (size_t)(r0 + row) * DM_ + h * 64 + seg * 8;
                asm volatile("cp.async.cg.shared.global [%0], [%1], 16;\n"
                             :: "r"(dst), "l"(sp_));
            }
        }
        const __half* pbuf[2] = {prjh, prjl};
#pragma unroll
        for (int buf = 0; buf < 2; buf++) {
#pragma unroll
            for (int j = 0; j < 4; j++) {
                const int c = tid + j * 256;
                const int row = c >> 3;
                const int seg = c & 7;
                const uint32_t dst = sb + (uint32_t)((4 + buf) * F3_AT + row * ROWB + seg * 16);
                asm volatile("cp.async.cg.shared.global [%0], [%1], 16;\n"
                             :: "r"(dst), "l"(pbuf[buf] + row * 64 + seg * 8));
            }
        }
        asm volatile("cp.async.commit_group;\n");
        asm volatile("cp.async.wait_group 0;\n");
        __syncthreads();
    }

    {
        const int r = tid >> 1;
        const int hf = tid & 1;
        const uint32_t boff_h = (uint32_t)(2 * F3_AT + r * ROWB + hf * 64);
        const uint32_t boff_l = (uint32_t)(3 * F3_AT + r * ROWB + hf * 64);
        float s2 = 0.0f;
#pragma unroll
        for (int j = 0; j < 16; j++) {
            __half2 vh = *(__half2*)(smem + boff_h + j * 4);
            __half2 vl = *(__half2*)(smem + boff_l + j * 4);
            const float a0 = __half2float(__low2half(vh)) + __half2float(__low2half(vl));
            const float a1 = __half2float(__high2half(vh)) + __half2float(__high2half(vl));
            s2 += a0 * a0 + a1 * a1;
        }
        nfp[tid] = s2;
    }
    __syncthreads();
    if (tid < 128) {
        const float v2 = nfp[tid * 2] + nfp[tid * 2 + 1];
        nf[(size_t)(r0 + tid) * H_ + h] = sqrtf(v2) * (1.0f / (float)L_);
    }

    const uint32_t a_off = (uint32_t)((((lane >> 3) & 1) * 8 + (lane & 7)) * ROWB
                                      + ((lane >> 4) * 8) * 2);
    const int bl_ = lane & 15;
    const uint32_t b_off = (uint32_t)(((bl_ & 7)) * ROWB + (((bl_ >> 3) & 1) * 8) * 2);

    float g1[16][4], g2[16][4];
#pragma unroll
    for (int i = 0; i < 16; i++)
#pragma unroll
        for (int q = 0; q < 4; q++) { g1[i][q] = 0.0f; g2[i][q] = 0.0f; }

    const uint32_t APH = sb;
    const uint32_t APL = sb + F3_AT;
    const uint32_t ASH = sb + 2 * F3_AT;
    const uint32_t ASL = sb + 3 * F3_AT;
    const uint32_t BH  = sb + 4 * F3_AT;
    const uint32_t BL  = sb + 5 * F3_AT;
    const uint32_t a_base = (uint32_t)(wid * 16 * ROWB) + a_off;

#pragma unroll
    for (int kk = 0; kk < 4; kk++) {
        const uint32_t kb = (uint32_t)(kk * 32);
        uint32_t aph[4], apl[4], ash[4], asl[4];
        ldmatrix_x4(aph, APH + a_base + kb);
        ldmatrix_x4(apl, APL + a_base + kb);
        ldmatrix_x4(ash, ASH + a_base + kb);
        ldmatrix_x4(asl, ASL + a_base + kb);
#pragma unroll
        for (int nf8 = 0; nf8 < 16; nf8++) {
            const uint32_t ro = (uint32_t)(nf8 * 8 * ROWB) + kb + b_off;
            uint32_t bh2[2], bl2[2];
            ldmatrix_x2(bh2, BH + ro);
            ldmatrix_x2(bl2, BL + ro);
            mma16816(g1[nf8], aph, bh2);
            mma16816(g1[nf8], apl, bh2);
            mma16816(g1[nf8], aph, bl2);
            mma16816(g2[nf8], ash, bh2);
            mma16816(g2[nf8], asl, bh2);
            mma16816(g2[nf8], ash, bl2);
        }
    }

    const int mrow = lane >> 2;
    const int ncol = (lane & 3) * 2;
    const uint32_t stage = sb + (uint32_t)(F3_STAGE_OFF + wid * 8192);

#pragma unroll
    for (int pass = 0; pass < 3; pass++) {
#pragma unroll
        for (int nf8 = 0; nf8 < 16; nf8++) {
#pragma unroll
            for (int hh = 0; hh < 2; hh++) {
                const int lr = mrow + hh * 8;
                const int m = nf8 * 8 + ncol;
                float d0, d1;
                if (pass == 0) {
                    d0 = s * g1[nf8][hh * 2 + 0];
                    d1 = s * g1[nf8][hh * 2 + 1];
                } else {
                    d0 = s * (g1[nf8][hh * 2 + 0] + off * g2[nf8][hh * 2 + 0]);
                    d1 = s * (g1[nf8][hh * 2 + 1] + off * g2[nf8][hh * 2 + 1]);
                }
                float s0, c0, s1, c1;
                __sincosf(d0, &s0, &c0);
                __sincosf(d1, &s1, &c1);
                s0 *= RATIO; c0 *= RATIO; s1 *= RATIO; c1 *= RATIO;
                __half2 vs, vc;
                if (pass < 2) {
                    vs = __halves2half2(__float2half_rn(s0), __float2half_rn(s1));
                    vc = __halves2half2(__float2half_rn(c0), __float2half_rn(c1));
                } else {
                    const __half hs0 = __float2half_rn(s0);
                    const __half hs1 = __float2half_rn(s1);
                    const __half hc0 = __float2half_rn(c0);
                    const __half hc1 = __float2half_rn(c1);
                    vs = __halves2half2(__float2half_rn(s0 - __half2float(hs0)),
                                        __float2half_rn(s1 - __half2float(hs1)));
                    vc = __halves2half2(__float2half_rn(c0 - __half2float(hc0)),
                                        __float2half_rn(c1 - __half2float(hc1)));
                }
                *(__half2*)(smem + (stage - sb) + lr * 512 + m * 2) = vs;
                *(__half2*)(smem + (stage - sb) + lr * 512 + (M_ + m) * 2) = vc;
            }
        }
        __syncwarp();
        __half* outp = (pass == 0) ? qp16 : (pass == 1 ? kh16 : kl16);
#pragma unroll
        for (int it = 0; it < 16; it++) {
            const int idx = lane + it * 32;
            const int lr = idx >> 5;
            const int seg = idx & 31;
            const uint4 v = *(uint4*)(smem + (stage - sb) + lr * 512 + seg * 16);
            *(uint4*)(outp + ((size_t)(r0 + wid * 16 + lr) * H_ + h) * (2 * M_)
                      + seg * 8) = v;
        }
        __syncwarp();
    }
}

// ===========================================================================
// kv_hmma (unchanged)
// ===========================================================================
#define KROWB 528
#define VROWB 144
#define KTB (64 * KROWB)
#define VTB (64 * VROWB)
#define KV_STAGE (2 * KTB + 2 * VTB)
#define KV_SMEM (2 * KV_STAGE)

__global__ __launch_bounds__(256, 1)
void kv_hmma_kernel(const __half* __restrict__ kh16, const __half* __restrict__ kl16,
                    const __half* __restrict__ vh16, const __half* __restrict__ vl16,
                    float* __restrict__ part)
{
    extern __shared__ char smem[];
    const uint32_t sb = smem_u32(smem);
    const int tid = threadIdx.x;
    const int wid = tid >> 5;
    const int lane = tid & 31;
    const int wm = wid & 3;
    const int wd = wid >> 2;
    const int chunk = blockIdx.x;
    const int h = blockIdx.y;
    const int b = blockIdx.z;
    const int lbase = chunk * LC_;

    const int grp = lane >> 3;
    const int lrow = lane & 7;
    const uint32_t a_off = (uint32_t)(((grp >> 1) * 8 + lrow) * KROWB
                                      + ((grp & 1) * 8) * 2);
    const int bl_ = lane & 15;
    const uint32_t b_off = (uint32_t)((((bl_ >> 3) * 8) + (bl_ & 7)) * VROWB);

    float acc[4][4][4];
#pragma unroll
    for (int i = 0; i < 4; i++)
#pragma unroll
        for (int j = 0; j < 4; j++)
#pragma unroll
            for (int q = 0; q < 4; q++) acc[i][j][q] = 0.0f;

    auto load_stage = [&](int s, int it) {
        const int l0 = lbase + it * 64;
        const uint32_t stage = sb + s * KV_STAGE;
#pragma unroll
        for (int j = 0; j < 8; j++) {
            const int c = tid + j * 256;
            const int row = c >> 5;
            const int seg = c & 31;
            const size_t src = ((size_t)(b * L_ + l0 + row) * H_ + h) * (2 * M_) + seg * 8;
            const uint32_t d0 = stage + (uint32_t)(row * KROWB + seg * 16);
            asm volatile("cp.async.cg.shared.global [%0], [%1], 16;\n"
                         :: "r"(d0), "l"(kh16 + src));
            asm volatile("cp.async.cg.shared.global [%0], [%1], 16;\n"
                         :: "r"(d0 + KTB), "l"(kl16 + src));
        }
#pragma unroll
        for (int j = 0; j < 2; j++) {
            const int c = tid + j * 256;
            const int row = c >> 3;
            const int seg = c & 7;
            const size_t src = (size_t)(b * L_ + l0 + row) * DM_ + h * 64 + seg * 8;
            const uint32_t d0 = stage + (uint32_t)(2 * KTB + row * VROWB + seg * 16);
            asm volatile("cp.async.cg.shared.global [%0], [%1], 16;\n"
                         :: "r"(d0), "l"(vh16 + src));
            asm volatile("cp.async.cg.shared.global [%0], [%1], 16;\n"
                         :: "r"(d0 + VTB), "l"(vl16 + src));
        }
        asm volatile("cp.async.commit_group;\n");
    };

    const int NIT = LC_ / 64;
    load_stage(0, 0);

    for (int it = 0; it < NIT; it++) {
        const int s = it & 1;
        if (it + 1 < NIT) {
            load_stage(s ^ 1, it + 1);
            asm volatile("cp.async.wait_group 1;\n");
        } else {
            asm volatile("cp.async.wait_group 0;\n");
        }
        __syncthreads();

        const uint32_t stage = sb + s * KV_STAGE;
        const uint32_t KH = stage;
        const uint32_t KL = stage + KTB;
        const uint32_t VH = stage + 2 * KTB;
        const uint32_t VL = VH + VTB;
        const uint32_t a_base = (uint32_t)((wm * 64) * 2) + a_off;
        const uint32_t b_base = (uint32_t)((wd * 32) * 2) + b_off;

#pragma unroll
        for (int kk = 0; kk < 4; kk++) {
            uint32_t akh[4][4], akl[4][4], bvh[4][2], bvl[4][2];
#pragma unroll
            for (int mf = 0; mf < 4; mf++) {
                const uint32_t ro = (uint32_t)(kk * 16 * KROWB) + a_base
                                    + (uint32_t)(mf * 16 * 2);
                ldmatrix_x4_t(akh[mf], KH + ro);
                ldmatrix_x4_t(akl[mf], KL + ro);
            }
#pragma unroll
            for (int nf = 0; nf < 4; nf++) {
                const uint32_t ro = (uint32_t)(kk * 16 * VROWB) + b_base
                                    + (uint32_t)(nf * 8 * 2);
                ldmatrix_x2_t(bvh[nf], VH + ro);
                ldmatrix_x2_t(bvl[nf], VL + ro);
            }
#pragma unroll
            for (int mf = 0; mf < 4; mf++)
#pragma unroll
                for (int nf = 0; nf < 4; nf++) {
                    mma16816(acc[mf][nf], akh[mf], bvh[nf]);
                    mma16816(acc[mf][nf], akl[mf], bvh[nf]);
                    mma16816(acc[mf][nf], akh[mf], bvl[nf]);
                }
        }
        __syncthreads();
    }

    const size_t pbase = ((size_t)((b * H_ + h) * NCHUNK + chunk)) * (2 * M_ * D_);
    const int mrow = lane >> 2;
    const int ncol = (lane & 3) * 2;
#pragma unroll
    for (int mf = 0; mf < 4; mf++) {
        const int m = wm * 64 + mf * 16 + mrow;
#pragma unroll
        for (int nf = 0; nf < 4; nf++) {
            const int d = wd * 32 + nf * 8 + ncol;
            *(float2*)(part + pbase + (size_t)m * D_ + d) =
                make_float2(acc[mf][nf][0], acc[mf][nf][1]);
            *(float2*)(part + pbase + (size_t)(m + 8) * D_ + d) =
                make_float2(acc[mf][nf][2], acc[mf][nf][3]);
        }
    }
}

__global__ __launch_bounds__(256)
void kv_reduce_kernel(const float* __restrict__ part, __half* __restrict__ kvt)
{
    const int idx = blockIdx.x * 256 + threadIdx.x;
    const int bh = idx / (2 * M_ * D_);
    const int md = idx % (2 * M_ * D_);
    float s = 0.0f;
#pragma unroll
    for (int c = 0; c < NCHUNK; c++)
        s += part[((size_t)bh * NCHUNK + c) * (2 * M_ * D_) + md];
    const int m = md >> 6;
    const int d = md & 63;
    kvt[((size_t)bh * D_ + d) * (2 * M_) + m] = __float2half_rn(s);
}

// ===========================================================================
// z_hmma — 2 CTAs/SM (unchanged from R11)
// ===========================================================================
#define ROWZB 528
#define ZA_BYTES (128 * ROWZB)
#define ZB_BYTES (64 * ROWZB)
#define Z_SMEM (ZA_BYTES + ZB_BYTES)

__global__ __launch_bounds__(256, 2)
void z_hmma_kernel(const __half* __restrict__ qp16, const __half* __restrict__ kvt,
                   const float* __restrict__ nf, __half* __restrict__ zh)
{
    extern __shared__ char smem[];
    const uint32_t sb = smem_u32(smem);
    const int tid = threadIdx.x;
    const int wid = tid >> 5;
    const int lane = tid & 31;
    const int lt = blockIdx.x;
    const int h = blockIdx.y;
    const int b = blockIdx.z;
    const int l0 = lt * 128;

    {
        const __half* src = qp16 + ((size_t)(b * L_ + l0) * H_ + h) * (2 * M_);
#pragma unroll
        for (int j = 0; j < 16; j++) {
            const int c = tid + j * 256;
            const int row = c >> 5;
            const int seg = c & 31;
            const uint32_t dst = sb + (uint32_t)(row * ROWZB + seg * 16);
            asm volatile("cp.async.cg.shared.global [%0], [%1], 16;\n"
                         :: "r"(dst), "l"(src + (size_t)row * H_ * (2 * M_) + seg * 8));
        }
    }
    {
        const __half* src = kvt + (size_t)(b * H_ + h) * D_ * (2 * M_);
#pragma unroll
        for (int j = 0; j < 8; j++) {
            const int c = tid + j * 256;
            const int row = c >> 5;
            const int seg = c & 31;
            const uint32_t dst = sb + (uint32_t)(ZA_BYTES + row * ROWZB + seg * 16);
            asm volatile("cp.async.cg.shared.global [%0], [%1], 16;\n"
                         :: "r"(dst), "l"(src + (size_t)row * (2 * M_) + seg * 8));
        }
    }
    asm volatile("cp.async.commit_group;\n");
    asm volatile("cp.async.wait_group 0;\n");
    __syncthreads();

    const uint32_t a_off = (uint32_t)((((lane >> 3) & 1) * 8 + (lane & 7)) * ROWZB
                                      + (lane >> 4) * 16);
    const int bl_ = lane & 15;
    const uint32_t b_off = (uint32_t)((bl_ & 7) * ROWZB + ((bl_ >> 3) & 1) * 16);

    float acc[8][4];
#pragma unroll
    for (int j = 0; j < 8; j++)
#pragma unroll
        for (int q = 0; q < 4; q++) acc[j][q] = 0.0f;

    const uint32_t a_base = sb + (uint32_t)(wid * 16 * ROWZB) + a_off;
    const uint32_t b_base = sb + ZA_BYTES + b_off;

#pragma unroll
    for (int kk = 0; kk < 16; kk++) {
        const uint32_t kb = (uint32_t)(kk * 32);
        uint32_t a[4];
        ldmatrix_x4(a, a_base + kb);
#pragma unroll
        for (int j = 0; j < 8; j++) {
            uint32_t bfr[2];
            ldmatrix_x2(bfr, b_base + (uint32_t)(j * 8 * ROWZB) + kb);
            mma16816(acc[j], a, bfr);
        }
    }

    const int mrow = lane >> 2;
    const int ncol = (lane & 3) * 2;
    const int gl0 = l0 + wid * 16 + mrow;
    const float f0 = nf[(size_t)(b * L_ + gl0) * H_ + h];
    const float f1 = nf[(size_t)(b * L_ + gl0 + 8) * H_ + h];
#pragma unroll
    for (int j = 0; j < 8; j++) {
        const int gn = h * 64 + j * 8 + ncol;
#pragma unroll
        for (int half = 0; half < 2; half++) {
            const int row = gl0 + half * 8;
            const float f = half ? f1 : f0;
            const float v0 = acc[j][half * 2 + 0] * f;
            const float v1 = acc[j][half * 2 + 1] * f;
            const size_t o = (size_t)(b * L_ + row) * DM_ + gn;
            *(__half2*)(zh + o) = __halves2half2(__float2half_rn(v0),
                                                 __float2half_rn(v1));
        }
    }
}

// ===========================================================================
extern "C" void kernel_launch(void* const* d_in, const int* in_sizes, int n_in,
                              void* d_out, int out_size)
{
    const float* x   = (const float*)d_in[0];
    const float* pft = (const float*)d_in[1];
    const float* psl = (const float*)d_in[2];
    const float* Wv  = (const float*)d_in[3];
    const float* Wo  = (const float*)d_in[4];
    const float* Wp  = (const float*)d_in[5];
    const float* sc  = (const float*)d_in[6];
    const float* ofs = (const float*)d_in[7];
    const float* prj = (const float*)d_in[8];
    float* out = (float*)d_out;

    float *ppart, *pnf;
    cudaGetSymbolAddress((void**)&ppart, g_part);
    cudaGetSymbolAddress((void**)&pnf,   g_nf);

    __half *pqp16, *pkh, *pkl, *pvh, *pvl, *pkvt;
    __half *ppph, *pppl, *psph, *pspl, *pprjh, *pprjl;
    cudaGetSymbolAddress((void**)&pqp16, g_qp16);
    cudaGetSymbolAddress((void**)&pkh,   g_kh16);
    cudaGetSymbolAddress((void**)&pkl,   g_kl16);
    cudaGetSymbolAddress((void**)&pvh,   g_vh16);
    cudaGetSymbolAddress((void**)&pvl,   g_vl16);
    cudaGetSymbolAddress((void**)&pkvt,  g_kvT16);
    cudaGetSymbolAddress((void**)&ppph,  g_pph);
    cudaGetSymbolAddress((void**)&pppl,  g_ppl);
    cudaGetSymbolAddress((void**)&psph,  g_sph);
    cudaGetSymbolAddress((void**)&pspl,  g_spl);
    cudaGetSymbolAddress((void**)&pprjh, g_prjh);
    cudaGetSymbolAddress((void**)&pprjl, g_prjl);

    __half *xh, *ph, *pl, *sh, *sl, *zh;
    __half *wvh, *wph, *wpl, *woh;
    cudaGetSymbolAddress((void**)&xh,  g_x16h);
    cudaGetSymbolAddress((void**)&ph,  g_p16h);
    cudaGetSymbolAddress((void**)&pl,  g_p16l);
    cudaGetSymbolAddress((void**)&sh,  g_s16h);
    cudaGetSymbolAddress((void**)&sl,  g_s16l);
    cudaGetSymbolAddress((void**)&zh,  g_z16h);
    cudaGetSymbolAddress((void**)&wvh, g_WvTh);
    cudaGetSymbolAddress((void**)&wph, g_WpTh);
    cudaGetSymbolAddress((void**)&wpl, g_WpTl);
    cudaGetSymbolAddress((void**)&woh, g_WoTh);

    cudaFuncSetAttribute(tc_gemm1, cudaFuncAttributeMaxDynamicSharedMemorySize,
                         G1_SMEM);
    cudaFuncSetAttribute(tc_gemm_pair, cudaFuncAttributeMaxDynamicSharedMemorySize,
                         GP_SMEM);
    cudaFuncSetAttribute(feat3_kernel, cudaFuncAttributeMaxDynamicSharedMemorySize,
                         F3_SMEM);
    cudaFuncSetAttribute(kv_hmma_kernel, cudaFuncAttributeMaxDynamicSharedMemorySize,
                         KV_SMEM);
    cudaFuncSetAttribute(z_hmma_kernel, cudaFuncAttributeMaxDynamicSharedMemorySize,
                         Z_SMEM);

    const int Mrows = B_ * L_;                       // 16384
    const int nsplit = (int)(NROW16 / 1024);

    split_all_kernel<<<dim3(nsplit, 3), 256>>>(x, pft, psl, xh, ph, pl, sh, sl);
    wtrans_all_kernel<<<dim3(DM_ / 32, DM_ / 32, 3), 256>>>(Wv, Wp, Wo,
                                                            wvh, wph, wpl, woh);
    proj_split_kernel<<<(M_ * D_ + 255) / 256, 256>>>(prj, pprjh, pprjl);

    dim3 gg(DM_ / 128, Mrows / 128);                 // (8, 128)
    tc_gemm1<<<gg, 256, G1_SMEM>>>(xh, wvh, (float*)0, pvh, pvl, DM_, DM_, 1);
    tc_gemm_pair<<<gg, 256, GP_SMEM>>>(ph, pl, sh, sl, wph, wpl,
                                       ppph, pppl, psph, pspl, DM_, DM_);

    feat3_kernel<<<dim3(Mrows / 128, H_), 256, F3_SMEM>>>(
        ppph, pppl, psph, pspl, pprjh, pprjl, sc, ofs, pqp16, pkh, pkl, pnf);

    kv_hmma_kernel<<<dim3(NCHUNK, H_, B_), 256, KV_SMEM>>>(pkh, pkl, pvh, pvl, ppart);
    kv_reduce_kernel<<<(B_ * H_ * 2 * M_ * D_) / 256, 256>>>(ppart, pkvt);

    z_hmma_kernel<<<dim3(L_ / 128, H_, B_), 256, Z_SMEM>>>(pqp16, pkvt, pnf, zh);

    tc_gemm1<<<gg, 256, G1_SMEM>>>(zh, woh, out, (__half*)0, (__half*)0, DM_, DM_, 0);
}

// round 15
// speedup vs baseline: 1.5122x; 1.5122x over previous
#include <cuda_runtime.h>
#include <cuda_fp16.h>
#include <cstdint>
#include <math.h>

// ---------------------------------------------------------------------------
// LinearSelfAttention — round 13: revert to R10 config (best: 1198us)
//   + z_hmma 2 CTAs/SM, fused split/wtrans launches (safe R11 tweaks)
//   tc_gemm1: 2-stage (R10). feat3: staged-store (R10).
//   (no numeric change: rel_err must stay 0.000748069)
// ---------------------------------------------------------------------------

#define B_ 4
#define L_ 4096
#define H_ 16
#define D_ 64
#define M_ 128
#define DM_ 1024
#define NCHUNK 8
#define LC_ (L_ / NCHUNK)    // 512

#define NORMALIZER 0.35355339059327373f
#define RATIO      0.08838834764831845f

// ----- fp32 scratch -----
__device__ float g_part[(size_t)B_ * H_ * NCHUNK * 2 * M_ * D_];
__device__ float g_nf  [(size_t)B_ * L_ * H_];

// ----- fp16 scratch -----
#define NROW16 ((size_t)B_ * L_ * DM_)
__device__ __half g_qp16 [(size_t)B_ * L_ * H_ * 2 * M_];
__device__ __half g_kh16 [(size_t)B_ * L_ * H_ * 2 * M_];
__device__ __half g_kl16 [(size_t)B_ * L_ * H_ * 2 * M_];
__device__ __half g_vh16 [NROW16];
__device__ __half g_vl16 [NROW16];
__device__ __half g_kvT16[(size_t)B_ * H_ * D_ * 2 * M_];
__device__ __half g_pph  [NROW16];
__device__ __half g_ppl  [NROW16];
__device__ __half g_sph  [NROW16];
__device__ __half g_spl  [NROW16];
__device__ __half g_prjh [(size_t)M_ * D_];
__device__ __half g_prjl [(size_t)M_ * D_];
__device__ __half g_x16h [NROW16];
__device__ __half g_p16h [NROW16];
__device__ __half g_p16l [NROW16];
__device__ __half g_s16h [NROW16];
__device__ __half g_s16l [NROW16];
__device__ __half g_z16h [NROW16];
__device__ __half g_WvTh [(size_t)DM_ * DM_];
__device__ __half g_WpTh [(size_t)DM_ * DM_];
__device__ __half g_WpTl [(size_t)DM_ * DM_];
__device__ __half g_WoTh [(size_t)DM_ * DM_];

// ===========================================================================
// PTX helpers
// ===========================================================================
__device__ __forceinline__ uint32_t smem_u32(const void* p) {
    uint32_t a;
    asm("{ .reg .u64 t; cvta.to.shared.u64 t, %1; cvt.u32.u64 %0, t; }"
        : "=r"(a) : "l"(p));
    return a;
}
__device__ __forceinline__ void ldmatrix_x4(uint32_t* r, uint32_t addr) {
    asm volatile("ldmatrix.sync.aligned.m8n8.x4.shared.b16 {%0,%1,%2,%3}, [%4];"
                 : "=r"(r[0]), "=r"(r[1]), "=r"(r[2]), "=r"(r[3]) : "r"(addr));
}
__device__ __forceinline__ void ldmatrix_x2(uint32_t* r, uint32_t addr) {
    asm volatile("ldmatrix.sync.aligned.m8n8.x2.shared.b16 {%0,%1}, [%2];"
                 : "=r"(r[0]), "=r"(r[1]) : "r"(addr));
}
__device__ __forceinline__ void ldmatrix_x4_t(uint32_t* r, uint32_t addr) {
    asm volatile("ldmatrix.sync.aligned.m8n8.x4.trans.shared.b16 {%0,%1,%2,%3}, [%4];"
                 : "=r"(r[0]), "=r"(r[1]), "=r"(r[2]), "=r"(r[3]) : "r"(addr));
}
__device__ __forceinline__ void ldmatrix_x2_t(uint32_t* r, uint32_t addr) {
    asm volatile("ldmatrix.sync.aligned.m8n8.x2.trans.shared.b16 {%0,%1}, [%2];"
                 : "=r"(r[0]), "=r"(r[1]) : "r"(addr));
}
__device__ __forceinline__ void mma16816(float* c, const uint32_t* a,
                                         const uint32_t* b) {
    asm volatile(
        "mma.sync.aligned.m16n8k16.row.col.f32.f16.f16.f32 "
        "{%0,%1,%2,%3}, {%4,%5,%6,%7}, {%8,%9}, {%0,%1,%2,%3};"
        : "+f"(c[0]), "+f"(c[1]), "+f"(c[2]), "+f"(c[3])
        : "r"(a[0]), "r"(a[1]), "r"(a[2]), "r"(a[3]), "r"(b[0]), "r"(b[1]));
}

#define KC_ 64
#define ROWB 144
#define TB_ (128 * ROWB)               // 18432 per 128x64 tile

// ===========================================================================
// tc_gemm1: C = A @ B^T, single term, 2-stage, 2 CTAs/SM (R10 version).
// ===========================================================================
#define G1_STAGE (2 * TB_)             // 36864
#define G1_SMEM (2 * G1_STAGE)         // 73728

__global__ __launch_bounds__(256, 2)
void tc_gemm1(const __half* __restrict__ A0, const __half* __restrict__ B0,
              float* __restrict__ C, __half* __restrict__ Ch,
              __half* __restrict__ Cl, int Nld, int K, int out16)
{
    extern __shared__ char smem[];
    const uint32_t sb = smem_u32(smem);
    const int tid = threadIdx.x;
    const int wid = tid >> 5;
    const int lane = tid & 31;
    const int wm = wid & 1;
    const int wn = wid >> 1;
    const int n0 = blockIdx.x * 128;
    const int m0 = blockIdx.y * 128;

    const uint32_t a_off = (uint32_t)((((lane >> 3) & 1) * 8 + (lane & 7)) * ROWB
                                      + ((lane >> 4) * 8) * 2);
    const int bl_ = lane & 15;
    const uint32_t b_off = (uint32_t)(((bl_ & 7)) * ROWB + (((bl_ >> 3) & 1) * 8) * 2);

    float acc[4][4][4];
#pragma unroll
    for (int i = 0; i < 4; i++)
#pragma unroll
        for (int j = 0; j < 4; j++)
#pragma unroll
            for (int q = 0; q < 4; q++) acc[i][j][q] = 0.0f;

    const int nch = K / KC_;

    auto load_stage = [&](int s, int chunk) {
        const int k0 = chunk * KC_;
        const uint32_t stage = sb + s * G1_STAGE;
#pragma unroll
        for (int buf = 0; buf < 2; buf++) {
            const __half* src = buf ? B0 : A0;
            const int r0 = buf ? n0 : m0;
            const uint32_t tb = stage + buf * TB_;
#pragma unroll
            for (int j = 0; j < 4; j++) {
                const int c = tid + j * 256;
                const int row = c >> 3;
                const int seg = c & 7;
                const uint32_t dst = tb + (uint32_t)(row * ROWB + seg * 16);
                const __half* sp = src + (size_t)(r0 + row) * K + k0 + seg * 8;
                asm volatile("cp.async.cg.shared.global [%0], [%1], 16;\n"
                             :: "r"(dst), "l"(sp));
            }
        }
        asm volatile("cp.async.commit_group;\n");
    };

    load_stage(0, 0);

    for (int i = 0; i < nch; i++) {
        const int s = i & 1;
        if (i + 1 < nch) {
            load_stage(s ^ 1, i + 1);
            asm volatile("cp.async.wait_group 1;\n");
        } else {
            asm volatile("cp.async.wait_group 0;\n");
        }
        __syncthreads();

        const uint32_t stage = sb + s * G1_STAGE;
        const uint32_t Ah = stage;
        const uint32_t Bh = stage + TB_;
        const uint32_t a_row = (uint32_t)(wm * 64 * ROWB);
        const uint32_t b_row = (uint32_t)(wn * 32 * ROWB);

#pragma unroll
        for (int kk = 0; kk < 4; kk++) {
            const uint32_t kb = (uint32_t)(kk * 32);
            uint32_t ah[4][4], bh[4][2];
#pragma unroll
            for (int mf = 0; mf < 4; mf++)
                ldmatrix_x4(ah[mf], Ah + a_row + (uint32_t)(mf * 16 * ROWB) + kb + a_off);
#pragma unroll
            for (int nf = 0; nf < 4; nf++)
                ldmatrix_x2(bh[nf], Bh + b_row + (uint32_t)(nf * 8 * ROWB) + kb + b_off);
#pragma unroll
            for (int mf = 0; mf < 4; mf++)
#pragma unroll
                for (int nf = 0; nf < 4; nf++)
                    mma16816(acc[mf][nf], ah[mf], bh[nf]);
        }
        __syncthreads();
    }

    const int mrow = lane >> 2;
    const int ncol = (lane & 3) * 2;
#pragma unroll
    for (int mf = 0; mf < 4; mf++) {
        const int gm = m0 + wm * 64 + mf * 16 + mrow;
#pragma unroll
        for (int nf = 0; nf < 4; nf++) {
            const int gn = n0 + wn * 32 + nf * 8 + ncol;
            if (!out16) {
                *(float2*)(C + (size_t)gm * Nld + gn) =
                    make_float2(acc[mf][nf][0], acc[mf][nf][1]);
                *(float2*)(C + (size_t)(gm + 8) * Nld + gn) =
                    make_float2(acc[mf][nf][2], acc[mf][nf][3]);
            } else {
#pragma unroll
                for (int hh = 0; hh < 2; hh++) {
                    const float v0 = acc[mf][nf][hh * 2 + 0];
                    const float v1 = acc[mf][nf][hh * 2 + 1];
                    const __half h0 = __float2half_rn(v0);
                    const __half h1 = __float2half_rn(v1);
                    const __half e0 = __float2half_rn(v0 - __half2float(h0));
                    const __half e1 = __float2half_rn(v1 - __half2float(h1));
                    const size_t o = (size_t)(gm + hh * 8) * Nld + gn;
                    *(__half2*)(Ch + o) = __halves2half2(h0, h1);
                    *(__half2*)(Cl + o) = __halves2half2(e0, e1);
                }
            }
        }
    }
}

// ===========================================================================
// tc_gemm_pair (unchanged from R10)
// ===========================================================================
#define GP_STAGE (6 * TB_)
#define GP_SMEM (2 * GP_STAGE)

__global__ __launch_bounds__(256, 1)
void tc_gemm_pair(const __half* __restrict__ Ap0, const __half* __restrict__ Ap1,
                  const __half* __restrict__ As0, const __half* __restrict__ As1,
                  const __half* __restrict__ B0, const __half* __restrict__ B1,
                  __half* __restrict__ Chp, __half* __restrict__ Clp,
                  __half* __restrict__ Chs, __half* __restrict__ Cls,
                  int Nld, int K)
{
    extern __shared__ char smem[];
    const uint32_t sb = smem_u32(smem);
    const int tid = threadIdx.x;
    const int wid = tid >> 5;
    const int lane = tid & 31;
    const int wm = wid & 1;
    const int wn = wid >> 1;
    const int n0 = blockIdx.x * 128;
    const int m0 = blockIdx.y * 128;

    const __half* srcs[6] = {Ap0, Ap1, As0, As1, B0, B1};

    const uint32_t a_off = (uint32_t)((((lane >> 3) & 1) * 8 + (lane & 7)) * ROWB
                                      + ((lane >> 4) * 8) * 2);
    const int bl_ = lane & 15;
    const uint32_t b_off = (uint32_t)(((bl_ & 7)) * ROWB + (((bl_ >> 3) & 1) * 8) * 2);

    float accp[4][4][4], accs[4][4][4];
#pragma unroll
    for (int i = 0; i < 4; i++)
#pragma unroll
        for (int j = 0; j < 4; j++)
#pragma unroll
            for (int q = 0; q < 4; q++) { accp[i][j][q] = 0.0f; accs[i][j][q] = 0.0f; }

    const int nch = K / KC_;

    auto load_stage = [&](int s, int chunk) {
        const int k0 = chunk * KC_;
        const uint32_t stage = sb + s * GP_STAGE;
#pragma unroll
        for (int buf = 0; buf < 6; buf++) {
            const __half* src = srcs[buf];
            const int r0 = (buf < 4) ? m0 : n0;
            const uint32_t tb = stage + buf * TB_;
#pragma unroll
            for (int j = 0; j < 4; j++) {
                const int c = tid + j * 256;
                const int row = c >> 3;
                const int seg = c & 7;
                const uint32_t dst = tb + (uint32_t)(row * ROWB + seg * 16);
                const __half* sp = src + (size_t)(r0 + row) * K + k0 + seg * 8;
                asm volatile("cp.async.cg.shared.global [%0], [%1], 16;\n"
                             :: "r"(dst), "l"(sp));
            }
        }
        asm volatile("cp.async.commit_group;\n");
    };

    load_stage(0, 0);

    for (int i = 0; i < nch; i++) {
        const int s = i & 1;
        if (i + 1 < nch) {
            load_stage(s ^ 1, i + 1);
            asm volatile("cp.async.wait_group 1;\n");
        } else {
            asm volatile("cp.async.wait_group 0;\n");
        }
        __syncthreads();

        const uint32_t stage = sb + s * GP_STAGE;
        const uint32_t Bh = stage + 4 * TB_;
        const uint32_t Bl = stage + 5 * TB_;
        const uint32_t a_row = (uint32_t)(wm * 64 * ROWB);
        const uint32_t b_row = (uint32_t)(wn * 32 * ROWB);

#pragma unroll
        for (int kk = 0; kk < 4; kk++) {
            const uint32_t kb = (uint32_t)(kk * 32);
            uint32_t bh[4][2], blr[4][2];
#pragma unroll
            for (int nf = 0; nf < 4; nf++) {
                const uint32_t ro = b_row + (uint32_t)(nf * 8 * ROWB) + kb + b_off;
                ldmatrix_x2(bh[nf], Bh + ro);
                ldmatrix_x2(blr[nf], Bl + ro);
            }
#pragma unroll
            for (int set = 0; set < 2; set++) {
                const uint32_t AH = stage + (set ? 2 : 0) * TB_;
                const uint32_t AL = stage + (set ? 3 : 1) * TB_;
                uint32_t ah[4][4], al[4][4];
#pragma unroll
                for (int mf = 0; mf < 4; mf++) {
                    const uint32_t ro = a_row + (uint32_t)(mf * 16 * ROWB) + kb + a_off;
                    ldmatrix_x4(ah[mf], AH + ro);
                    ldmatrix_x4(al[mf], AL + ro);
                }
#pragma unroll
                for (int mf = 0; mf < 4; mf++)
#pragma unroll
                    for (int nf = 0; nf < 4; nf++) {
                        if (set == 0) {
                            mma16816(accp[mf][nf], ah[mf], bh[nf]);
                            mma16816(accp[mf][nf], al[mf], bh[nf]);
                            mma16816(accp[mf][nf], ah[mf], blr[nf]);
                        } else {
                            mma16816(accs[mf][nf], ah[mf], bh[nf]);
                            mma16816(accs[mf][nf], al[mf], bh[nf]);
                            mma16816(accs[mf][nf], ah[mf], blr[nf]);
                        }
                    }
            }
        }
        __syncthreads();
    }

    const int mrow = lane >> 2;
    const int ncol = (lane & 3) * 2;
#pragma unroll
    for (int set = 0; set < 2; set++) {
        __half* Ch = set ? Chs : Chp;
        __half* Cl = set ? Cls : Clp;
#pragma unroll
        for (int mf = 0; mf < 4; mf++) {
            const int gm = m0 + wm * 64 + mf * 16 + mrow;
#pragma unroll
            for (int nf = 0; nf < 4; nf++) {
                const int gn = n0 + wn * 32 + nf * 8 + ncol;
#pragma unroll
                for (int hh = 0; hh < 2; hh++) {
                    const float v0 = set ? accs[mf][nf][hh * 2 + 0]
                                         : accp[mf][nf][hh * 2 + 0];
                    const float v1 = set ? accs[mf][nf][hh * 2 + 1]
                                         : accp[mf][nf][hh * 2 + 1];
                    const __half h0 = __float2half_rn(v0);
                    const __half h1 = __float2half_rn(v1);
                    const __half e0 = __float2half_rn(v0 - __half2float(h0));
                    const __half e1 = __float2half_rn(v1 - __half2float(h1));
                    const size_t o = (size_t)(gm + hh * 8) * Nld + gn;
                    *(__half2*)(Ch + o) = __halves2half2(h0, h1);
                    *(__half2*)(Cl + o) = __halves2half2(e0, e1);
                }
            }
        }
    }
}

// ===========================================================================
// fused split / transpose helpers
// ===========================================================================
__global__ __launch_bounds__(256)
void split_all_kernel(const float* __restrict__ x, const float* __restrict__ pft,
                      const float* __restrict__ psl,
                      __half* __restrict__ xh, __half* __restrict__ ph,
                      __half* __restrict__ pl, __half* __restrict__ sh,
                      __half* __restrict__ sl)
{
    const int z = blockIdx.y;
    const float* src = (z == 0) ? x : (z == 1 ? pft : psl);
    __half* hi = (z == 0) ? xh : (z == 1 ? ph : sh);
    __half* lo = (z == 1) ? pl : sl;

    const size_t i0 = ((size_t)blockIdx.x * 256 + threadIdx.x) * 4;
    float4 v = *(const float4*)(src + i0);
    float f[4] = {v.x, v.y, v.z, v.w};
    __half ha0 = __float2half_rn(f[0]);
    __half ha1 = __float2half_rn(f[1]);
    __half ha2 = __float2half_rn(f[2]);
    __half ha3 = __float2half_rn(f[3]);
    *(__half2*)(hi + i0)     = __halves2half2(ha0, ha1);
    *(__half2*)(hi + i0 + 2) = __halves2half2(ha2, ha3);
    if (z != 0) {
        *(__half2*)(lo + i0) = __halves2half2(
            __float2half_rn(f[0] - __half2float(ha0)),
            __float2half_rn(f[1] - __half2float(ha1)));
        *(__half2*)(lo + i0 + 2) = __halves2half2(
            __float2half_rn(f[2] - __half2float(ha2)),
            __float2half_rn(f[3] - __half2float(ha3)));
    }
}

__global__ __launch_bounds__(256)
void wtrans_all_kernel(const float* __restrict__ Wv, const float* __restrict__ Wp,
                       const float* __restrict__ Wo,
                       __half* __restrict__ wvh, __half* __restrict__ wph,
                       __half* __restrict__ wpl, __half* __restrict__ woh)
{
    const int z = blockIdx.z;
    const float* W = (z == 0) ? Wv : (z == 1 ? Wp : Wo);
    __half* th = (z == 0) ? wvh : (z == 1 ? wph : woh);
    __half* tl = (z == 1) ? wpl : (__half*)0;

    __shared__ float tile[32][33];
    const int tx = threadIdx.x & 31;
    const int ty = threadIdx.x >> 5;
    const int n0 = blockIdx.x * 32;
    const int k0 = blockIdx.y * 32;
#pragma unroll
    for (int i = 0; i < 4; i++)
        tile[ty + i * 8][tx] = W[(size_t)(k0 + ty + i * 8) * DM_ + n0 + tx];
    __syncthreads();
#pragma unroll
    for (int i = 0; i < 4; i++) {
        const int n = ty + i * 8;
        float v = tile[tx][n];
        __half h = __float2half_rn(v);
        const size_t o = (size_t)(n0 + n) * DM_ + k0 + tx;
        th[o] = h;
        if (tl) tl[o] = __float2half_rn(v - __half2float(h));
    }
}

__global__ __launch_bounds__(256)
void proj_split_kernel(const float* __restrict__ proj, __half* __restrict__ ph,
                       __half* __restrict__ pl)
{
    const int i = blockIdx.x * 256 + threadIdx.x;
    if (i < M_ * D_) {
        const float v = NORMALIZER * proj[i];
        const __half h = __float2half_rn(v);
        ph[i] = h;
        pl[i] = __float2half_rn(v - __half2float(h));
    }
}

// ===========================================================================
// feat3 — R10 staged-store version (coalesced epilogue), 1 CTA/SM
// ===========================================================================
#define F3_AT (128 * ROWB)
#define F3_STAGE_OFF (6 * F3_AT)
#define F3_SMEM (F3_STAGE_OFF + 8 * 16 * 256 * 2)   // 176128

__global__ __launch_bounds__(256, 1)
void feat3_kernel(const __half* __restrict__ pph, const __half* __restrict__ ppl,
                  const __half* __restrict__ sph, const __half* __restrict__ spl,
                  const __half* __restrict__ prjh, const __half* __restrict__ prjl,
                  const float* __restrict__ scale, const float* __restrict__ offs,
                  __half* __restrict__ qp16, __half* __restrict__ kh16,
                  __half* __restrict__ kl16, float* __restrict__ nf)
{
    extern __shared__ char smem[];
    __shared__ float nfp[256];
    const uint32_t sb = smem_u32(smem);
    const int tid = threadIdx.x;
    const int wid = tid >> 5;
    const int lane = tid & 31;
    const int h = blockIdx.y;
    const int r0 = blockIdx.x * 128;
    const float s = scale[h];
    const float off = offs[h];

    {
        const __half* abuf[4] = {pph, ppl, sph, spl};
#pragma unroll
        for (int buf = 0; buf < 4; buf++) {
#pragma unroll
            for (int j = 0; j < 4; j++) {
                const int c = tid + j * 256;
                const int row = c >> 3;
                const int seg = c & 7;
                const uint32_t dst = sb + (uint32_t)(buf * F3_AT + row * ROWB + seg * 16);
                const __half* sp_ = abuf[buf] + (size_t)(r0 + row) * DM_ + h * 64 + seg * 8;
                asm volatile("cp.async.cg.shared.global [%0], [%1], 16;\n"
                             :: "r"(dst), "l"(sp_));
            }
        }
        const __half* pbuf[2] = {prjh, prjl};
#pragma unroll
        for (int buf = 0; buf < 2; buf++) {
#pragma unroll
            for (int j = 0; j < 4; j++) {
                const int c = tid + j * 256;
                const int row = c >> 3;
                const int seg = c & 7;
                const uint32_t dst = sb + (uint32_t)((4 + buf) * F3_AT + row * ROWB + seg * 16);
                asm volatile("cp.async.cg.shared.global [%0], [%1], 16;\n"
                             :: "r"(dst), "l"(pbuf[buf] + row * 64 + seg * 8));
            }
        }
        asm volatile("cp.async.commit_group;\n");
        asm volatile("cp.async.wait_group 0;\n");
        __syncthreads();
    }

    {
        const int r = tid >> 1;
        const int hf = tid & 1;
        const uint32_t boff_h = (uint32_t)(2 * F3_AT + r * ROWB + hf * 64);
        const uint32_t boff_l = (uint32_t)(3 * F3_AT + r * ROWB + hf * 64);
        float s2 = 0.0f;
#pragma unroll
        for (int j = 0; j < 16; j++) {
            __half2 vh = *(__half2*)(smem + boff_h + j * 4);
            __half2 vl = *(__half2*)(smem + boff_l + j * 4);
            const float a0 = __half2float(__low2half(vh)) + __half2float(__low2half(vl));
            const float a1 = __half2float(__high2half(vh)) + __half2float(__high2half(vl));
            s2 += a0 * a0 + a1 * a1;
        }
        nfp[tid] = s2;
    }
    __syncthreads();
    if (tid < 128) {
        const float v2 = nfp[tid * 2] + nfp[tid * 2 + 1];
        nf[(size_t)(r0 + tid) * H_ + h] = sqrtf(v2) * (1.0f / (float)L_);
    }

    const uint32_t a_off = (uint32_t)((((lane >> 3) & 1) * 8 + (lane & 7)) * ROWB
                                      + ((lane >> 4) * 8) * 2);
    const int bl_ = lane & 15;
    const uint32_t b_off = (uint32_t)(((bl_ & 7)) * ROWB + (((bl_ >> 3) & 1) * 8) * 2);

    float g1[16][4], g2[16][4];
#pragma unroll
    for (int i = 0; i < 16; i++)
#pragma unroll
        for (int q = 0; q < 4; q++) { g1[i][q] = 0.0f; g2[i][q] = 0.0f; }

    const uint32_t APH = sb;
    const uint32_t APL = sb + F3_AT;
    const uint32_t ASH = sb + 2 * F3_AT;
    const uint32_t ASL = sb + 3 * F3_AT;
    const uint32_t BH  = sb + 4 * F3_AT;
    const uint32_t BL  = sb + 5 * F3_AT;
    const uint32_t a_base = (uint32_t)(wid * 16 * ROWB) + a_off;

#pragma unroll
    for (int kk = 0; kk < 4; kk++) {
        const uint32_t kb = (uint32_t)(kk * 32);
        uint32_t aph[4], apl[4], ash[4], asl[4];
        ldmatrix_x4(aph, APH + a_base + kb);
        ldmatrix_x4(apl, APL + a_base + kb);
        ldmatrix_x4(ash, ASH + a_base + kb);
        ldmatrix_x4(asl, ASL + a_base + kb);
#pragma unroll
        for (int nf8 = 0; nf8 < 16; nf8++) {
            const uint32_t ro = (uint32_t)(nf8 * 8 * ROWB) + kb + b_off;
            uint32_t bh2[2], bl2[2];
            ldmatrix_x2(bh2, BH + ro);
            ldmatrix_x2(bl2, BL + ro);
            mma16816(g1[nf8], aph, bh2);
            mma16816(g1[nf8], apl, bh2);
            mma16816(g1[nf8], aph, bl2);
            mma16816(g2[nf8], ash, bh2);
            mma16816(g2[nf8], asl, bh2);
            mma16816(g2[nf8], ash, bl2);
        }
    }

    const int mrow = lane >> 2;
    const int ncol = (lane & 3) * 2;
    const uint32_t stage = sb + (uint32_t)(F3_STAGE_OFF + wid * 8192);

#pragma unroll
    for (int pass = 0; pass < 3; pass++) {
#pragma unroll
        for (int nf8 = 0; nf8 < 16; nf8++) {
#pragma unroll
            for (int hh = 0; hh < 2; hh++) {
                const int lr = mrow + hh * 8;
                const int m = nf8 * 8 + ncol;
                float d0, d1;
                if (pass == 0) {
                    d0 = s * g1[nf8][hh * 2 + 0];
                    d1 = s * g1[nf8][hh * 2 + 1];
                } else {
                    d0 = s * (g1[nf8][hh * 2 + 0] + off * g2[nf8][hh * 2 + 0]);
                    d1 = s * (g1[nf8][hh * 2 + 1] + off * g2[nf8][hh * 2 + 1]);
                }
                float s0, c0, s1, c1;
                __sincosf(d0, &s0, &c0);
                __sincosf(d1, &s1, &c1);
                s0 *= RATIO; c0 *= RATIO; s1 *= RATIO; c1 *= RATIO;
                __half2 vs, vc;
                if (pass < 2) {
                    vs = __halves2half2(__float2half_rn(s0), __float2half_rn(s1));
                    vc = __halves2half2(__float2half_rn(c0), __float2half_rn(c1));
                } else {
                    const __half hs0 = __float2half_rn(s0);
                    const __half hs1 = __float2half_rn(s1);
                    const __half hc0 = __float2half_rn(c0);
                    const __half hc1 = __float2half_rn(c1);
                    vs = __halves2half2(__float2half_rn(s0 - __half2float(hs0)),
                                        __float2half_rn(s1 - __half2float(hs1)));
                    vc = __halves2half2(__float2half_rn(c0 - __half2float(hc0)),
                                        __float2half_rn(c1 - __half2float(hc1)));
                }
                *(__half2*)(smem + (stage - sb) + lr * 512 + m * 2) = vs;
                *(__half2*)(smem + (stage - sb) + lr * 512 + (M_ + m) * 2) = vc;
            }
        }
        __syncwarp();
        __half* outp = (pass == 0) ? qp16 : (pass == 1 ? kh16 : kl16);
#pragma unroll
        for (int it = 0; it < 16; it++) {
            const int idx = lane + it * 32;
            const int lr = idx >> 5;
            const int seg = idx & 31;
            const uint4 v = *(uint4*)(smem + (stage - sb) + lr * 512 + seg * 16);
            *(uint4*)(outp + ((size_t)(r0 + wid * 16 + lr) * H_ + h) * (2 * M_)
                      + seg * 8) = v;
        }
        __syncwarp();
    }
}

// ===========================================================================
// kv_hmma (unchanged)
// ===========================================================================
#define KROWB 528
#define VROWB 144
#define KTB (64 * KROWB)
#define VTB (64 * VROWB)
#define KV_STAGE (2 * KTB + 2 * VTB)
#define KV_SMEM (2 * KV_STAGE)

__global__ __launch_bounds__(256, 1)
void kv_hmma_kernel(const __half* __restrict__ kh16, const __half* __restrict__ kl16,
                    const __half* __restrict__ vh16, const __half* __restrict__ vl16,
                    float* __restrict__ part)
{
    extern __shared__ char smem[];
    const uint32_t sb = smem_u32(smem);
    const int tid = threadIdx.x;
    const int wid = tid >> 5;
    const int lane = tid & 31;
    const int wm = wid & 3;
    const int wd = wid >> 2;
    const int chunk = blockIdx.x;
    const int h = blockIdx.y;
    const int b = blockIdx.z;
    const int lbase = chunk * LC_;

    const int grp = lane >> 3;
    const int lrow = lane & 7;
    const uint32_t a_off = (uint32_t)(((grp >> 1) * 8 + lrow) * KROWB
                                      + ((grp & 1) * 8) * 2);
    const int bl_ = lane & 15;
    const uint32_t b_off = (uint32_t)((((bl_ >> 3) * 8) + (bl_ & 7)) * VROWB);

    float acc[4][4][4];
#pragma unroll
    for (int i = 0; i < 4; i++)
#pragma unroll
        for (int j = 0; j < 4; j++)
#pragma unroll
            for (int q = 0; q < 4; q++) acc[i][j][q] = 0.0f;

    auto load_stage = [&](int s, int it) {
        const int l0 = lbase + it * 64;
        const uint32_t stage = sb + s * KV_STAGE;
#pragma unroll
        for (int j = 0; j < 8; j++) {
            const int c = tid + j * 256;
            const int row = c >> 5;
            const int seg = c & 31;
            const size_t src = ((size_t)(b * L_ + l0 + row) * H_ + h) * (2 * M_) + seg * 8;
            const uint32_t d0 = stage + (uint32_t)(row * KROWB + seg * 16);
            asm volatile("cp.async.cg.shared.global [%0], [%1], 16;\n"
                         :: "r"(d0), "l"(kh16 + src));
            asm volatile("cp.async.cg.shared.global [%0], [%1], 16;\n"
                         :: "r"(d0 + KTB), "l"(kl16 + src));
        }
#pragma unroll
        for (int j = 0; j < 2; j++) {
            const int c = tid + j * 256;
            const int row = c >> 3;
            const int seg = c & 7;
            const size_t src = (size_t)(b * L_ + l0 + row) * DM_ + h * 64 + seg * 8;
            const uint32_t d0 = stage + (uint32_t)(2 * KTB + row * VROWB + seg * 16);
            asm volatile("cp.async.cg.shared.global [%0], [%1], 16;\n"
                         :: "r"(d0), "l"(vh16 + src));
            asm volatile("cp.async.cg.shared.global [%0], [%1], 16;\n"
                         :: "r"(d0 + VTB), "l"(vl16 + src));
        }
        asm volatile("cp.async.commit_group;\n");
    };

    const int NIT = LC_ / 64;
    load_stage(0, 0);

    for (int it = 0; it < NIT; it++) {
        const int s = it & 1;
        if (it + 1 < NIT) {
            load_stage(s ^ 1, it + 1);
            asm volatile("cp.async.wait_group 1;\n");
        } else {
            asm volatile("cp.async.wait_group 0;\n");
        }
        __syncthreads();

        const uint32_t stage = sb + s * KV_STAGE;
        const uint32_t KH = stage;
        const uint32_t KL = stage + KTB;
        const uint32_t VH = stage + 2 * KTB;
        const uint32_t VL = VH + VTB;
        const uint32_t a_base = (uint32_t)((wm * 64) * 2) + a_off;
        const uint32_t b_base = (uint32_t)((wd * 32) * 2) + b_off;

#pragma unroll
        for (int kk = 0; kk < 4; kk++) {
            uint32_t akh[4][4], akl[4][4], bvh[4][2], bvl[4][2];
#pragma unroll
            for (int mf = 0; mf < 4; mf++) {
                const uint32_t ro = (uint32_t)(kk * 16 * KROWB) + a_base
                                    + (uint32_t)(mf * 16 * 2);
                ldmatrix_x4_t(akh[mf], KH + ro);
                ldmatrix_x4_t(akl[mf], KL + ro);
            }
#pragma unroll
            for (int nf = 0; nf < 4; nf++) {
                const uint32_t ro = (uint32_t)(kk * 16 * VROWB) + b_base
                                    + (uint32_t)(nf * 8 * 2);
                ldmatrix_x2_t(bvh[nf], VH + ro);
                ldmatrix_x2_t(bvl[nf], VL + ro);
            }
#pragma unroll
            for (int mf = 0; mf < 4; mf++)
#pragma unroll
                for (int nf = 0; nf < 4; nf++) {
                    mma16816(acc[mf][nf], akh[mf], bvh[nf]);
                    mma16816(acc[mf][nf], akl[mf], bvh[nf]);
                    mma16816(acc[mf][nf], akh[mf], bvl[nf]);
                }
        }
        __syncthreads();
    }

    const size_t pbase = ((size_t)((b * H_ + h) * NCHUNK + chunk)) * (2 * M_ * D_);
    const int mrow = lane >> 2;
    const int ncol = (lane & 3) * 2;
#pragma unroll
    for (int mf = 0; mf < 4; mf++) {
        const int m = wm * 64 + mf * 16 + mrow;
#pragma unroll
        for (int nf = 0; nf < 4; nf++) {
            const int d = wd * 32 + nf * 8 + ncol;
            *(float2*)(part + pbase + (size_t)m * D_ + d) =
                make_float2(acc[mf][nf][0], acc[mf][nf][1]);
            *(float2*)(part + pbase + (size_t)(m + 8) * D_ + d) =
                make_float2(acc[mf][nf][2], acc[mf][nf][3]);
        }
    }
}

__global__ __launch_bounds__(256)
void kv_reduce_kernel(const float* __restrict__ part, __half* __restrict__ kvt)
{
    const int idx = blockIdx.x * 256 + threadIdx.x;
    const int bh = idx / (2 * M_ * D_);
    const int md = idx % (2 * M_ * D_);
    float s = 0.0f;
#pragma unroll
    for (int c = 0; c < NCHUNK; c++)
        s += part[((size_t)bh * NCHUNK + c) * (2 * M_ * D_) + md];
    const int m = md >> 6;
    const int d = md & 63;
    kvt[((size_t)bh * D_ + d) * (2 * M_) + m] = __float2half_rn(s);
}

// ===========================================================================
// z_hmma — 2 CTAs/SM
// ===========================================================================
#define ROWZB 528
#define ZA_BYTES (128 * ROWZB)
#define ZB_BYTES (64 * ROWZB)
#define Z_SMEM (ZA_BYTES + ZB_BYTES)

__global__ __launch_bounds__(256, 2)
void z_hmma_kernel(const __half* __restrict__ qp16, const __half* __restrict__ kvt,
                   const float* __restrict__ nf, __half* __restrict__ zh)
{
    extern __shared__ char smem[];
    const uint32_t sb = smem_u32(smem);
    const int tid = threadIdx.x;
    const int wid = tid >> 5;
    const int lane = tid & 31;
    const int lt = blockIdx.x;
    const int h = blockIdx.y;
    const int b = blockIdx.z;
    const int l0 = lt * 128;

    {
        const __half* src = qp16 + ((size_t)(b * L_ + l0) * H_ + h) * (2 * M_);
#pragma unroll
        for (int j = 0; j < 16; j++) {
            const int c = tid + j * 256;
            const int row = c >> 5;
            const int seg = c & 31;
            const uint32_t dst = sb + (uint32_t)(row * ROWZB + seg * 16);
            asm volatile("cp.async.cg.shared.global [%0], [%1], 16;\n"
                         :: "r"(dst), "l"(src + (size_t)row * H_ * (2 * M_) + seg * 8));
        }
    }
    {
        const __half* src = kvt + (size_t)(b * H_ + h) * D_ * (2 * M_);
#pragma unroll
        for (int j = 0; j < 8; j++) {
            const int c = tid + j * 256;
            const int row = c >> 5;
            const int seg = c & 31;
            const uint32_t dst = sb + (uint32_t)(ZA_BYTES + row * ROWZB + seg * 16);
            asm volatile("cp.async.cg.shared.global [%0], [%1], 16;\n"
                         :: "r"(dst), "l"(src + (size_t)row * (2 * M_) + seg * 8));
        }
    }
    asm volatile("cp.async.commit_group;\n");
    asm volatile("cp.async.wait_group 0;\n");
    __syncthreads();

    const uint32_t a_off = (uint32_t)((((lane >> 3) & 1) * 8 + (lane & 7)) * ROWZB
                                      + (lane >> 4) * 16);
    const int bl_ = lane & 15;
    const uint32_t b_off = (uint32_t)((bl_ & 7) * ROWZB + ((bl_ >> 3) & 1) * 16);

    float acc[8][4];
#pragma unroll
    for (int j = 0; j < 8; j++)
#pragma unroll
        for (int q = 0; q < 4; q++) acc[j][q] = 0.0f;

    const uint32_t a_base = sb + (uint32_t)(wid * 16 * ROWZB) + a_off;
    const uint32_t b_base = sb + ZA_BYTES + b_off;

#pragma unroll
    for (int kk = 0; kk < 16; kk++) {
        const uint32_t kb = (uint32_t)(kk * 32);
        uint32_t a[4];
        ldmatrix_x4(a, a_base + kb);
#pragma unroll
        for (int j = 0; j < 8; j++) {
            uint32_t bfr[2];
            ldmatrix_x2(bfr, b_base + (uint32_t)(j * 8 * ROWZB) + kb);
            mma16816(acc[j], a, bfr);
        }
    }

    const int mrow = lane >> 2;
    const int ncol = (lane & 3) * 2;
    const int gl0 = l0 + wid * 16 + mrow;
    const float f0 = nf[(size_t)(b * L_ + gl0) * H_ + h];
    const float f1 = nf[(size_t)(b * L_ + gl0 + 8) * H_ + h];
#pragma unroll
    for (int j = 0; j < 8; j++) {
        const int gn = h * 64 + j * 8 + ncol;
#pragma unroll
        for (int half = 0; half < 2; half++) {
            const int row = gl0 + half * 8;
            const float f = half ? f1 : f0;
            const float v0 = acc[j][half * 2 + 0] * f;
            const float v1 = acc[j][half * 2 + 1] * f;
            const size_t o = (size_t)(b * L_ + row) * DM_ + gn;
            *(__half2*)(zh + o) = __halves2half2(__float2half_rn(v0),
                                                 __float2half_rn(v1));
        }
    }
}

// ===========================================================================
extern "C" void kernel_launch(void* const* d_in, const int* in_sizes, int n_in,
                              void* d_out, int out_size)
{
    const float* x   = (const float*)d_in[0];
    const float* pft = (const float*)d_in[1];
    const float* psl = (const float*)d_in[2];
    const float* Wv  = (const float*)d_in[3];
    const float* Wo  = (const float*)d_in[4];
    const float* Wp  = (const float*)d_in[5];
    const float* sc  = (const float*)d_in[6];
    const float* ofs = (const float*)d_in[7];
    const float* prj = (const float*)d_in[8];
    float* out = (float*)d_out;

    float *ppart, *pnf;
    cudaGetSymbolAddress((void**)&ppart, g_part);
    cudaGetSymbolAddress((void**)&pnf,   g_nf);

    __half *pqp16, *pkh, *pkl, *pvh, *pvl, *pkvt;
    __half *ppph, *pppl, *psph, *pspl, *pprjh, *pprjl;
    cudaGetSymbolAddress((void**)&pqp16, g_qp16);
    cudaGetSymbolAddress((void**)&pkh,   g_kh16);
    cudaGetSymbolAddress((void**)&pkl,   g_kl16);
    cudaGetSymbolAddress((void**)&pvh,   g_vh16);
    cudaGetSymbolAddress((void**)&pvl,   g_vl16);
    cudaGetSymbolAddress((void**)&pkvt,  g_kvT16);
    cudaGetSymbolAddress((void**)&ppph,  g_pph);
    cudaGetSymbolAddress((void**)&pppl,  g_ppl);
    cudaGetSymbolAddress((void**)&psph,  g_sph);
    cudaGetSymbolAddress((void**)&pspl,  g_spl);
    cudaGetSymbolAddress((void**)&pprjh, g_prjh);
    cudaGetSymbolAddress((void**)&pprjl, g_prjl);

    __half *xh, *ph, *pl, *sh, *sl, *zh;
    __half *wvh, *wph, *wpl, *woh;
    cudaGetSymbolAddress((void**)&xh,  g_x16h);
    cudaGetSymbolAddress((void**)&ph,  g_p16h);
    cudaGetSymbolAddress((void**)&pl,  g_p16l);
    cudaGetSymbolAddress((void**)&sh,  g_s16h);
    cudaGetSymbolAddress((void**)&sl,  g_s16l);
    cudaGetSymbolAddress((void**)&zh,  g_z16h);
    cudaGetSymbolAddress((void**)&wvh, g_WvTh);
    cudaGetSymbolAddress((void**)&wph, g_WpTh);
    cudaGetSymbolAddress((void**)&wpl, g_WpTl);
    cudaGetSymbolAddress((void**)&woh, g_WoTh);

    cudaFuncSetAttribute(tc_gemm1, cudaFuncAttributeMaxDynamicSharedMemorySize,
                         G1_SMEM);
    cudaFuncSetAttribute(tc_gemm_pair, cudaFuncAttributeMaxDynamicSharedMemorySize,
                         GP_SMEM);
    cudaFuncSetAttribute(feat3_kernel, cudaFuncAttributeMaxDynamicSharedMemorySize,
                         F3_SMEM);
    cudaFuncSetAttribute(kv_hmma_kernel, cudaFuncAttributeMaxDynamicSharedMemorySize,
                         KV_SMEM);
    cudaFuncSetAttribute(z_hmma_kernel, cudaFuncAttributeMaxDynamicSharedMemorySize,
                         Z_SMEM);

    const int Mrows = B_ * L_;                       // 16384
    const int nsplit = (int)(NROW16 / 1024);

    split_all_kernel<<<dim3(nsplit, 3), 256>>>(x, pft, psl, xh, ph, pl, sh, sl);
    wtrans_all_kernel<<<dim3(DM_ / 32, DM_ / 32, 3), 256>>>(Wv, Wp, Wo,
                                                            wvh, wph, wpl, woh);
    proj_split_kernel<<<(M_ * D_ + 255) / 256, 256>>>(prj, pprjh, pprjl);

    dim3 gg(DM_ / 128, Mrows / 128);                 // (8, 128)
    tc_gemm1<<<gg, 256, G1_SMEM>>>(xh, wvh, (float*)0, pvh, pvl, DM_, DM_, 1);
    tc_gemm_pair<<<gg, 256, GP_SMEM>>>(ph, pl, sh, sl, wph, wpl,
                                       ppph, pppl, psph, pspl, DM_, DM_);

    feat3_kernel<<<dim3(Mrows / 128, H_), 256, F3_SMEM>>>(
        ppph, pppl, psph, pspl, pprjh, pprjl, sc, ofs, pqp16, pkh, pkl, pnf);

    kv_hmma_kernel<<<dim3(NCHUNK, H_, B_), 256, KV_SMEM>>>(pkh, pkl, pvh, pvl, ppart);
    kv_reduce_kernel<<<(B_ * H_ * 2 * M_ * D_) / 256, 256>>>(ppart, pkvt);

    z_hmma_kernel<<<dim3(L_ / 128, H_, B_), 256, Z_SMEM>>>(pqp16, pkvt, pnf, zh);

    tc_gemm1<<<gg, 256, G1_SMEM>>>(zh, woh, out, (__half*)0, (__half*)0, DM_, DM_, 0);
}